// round 4
// baseline (speedup 1.0000x reference)
#include <cuda_runtime.h>
#include <cuda_bf16.h>
#include <math.h>

#define TT 8
#define NNODE 40000
#define FF 256
#define PP 128
#define GG 128
#define HH 128
#define BB 1024
#define NE 640000
#define NNZ (NE + NNODE)

// ------------------------- device scratch (16B aligned, accessed by symbol only) ---
__device__ __align__(16) float g_h  [(size_t)NNODE * PP];
__device__ __align__(16) float g_m  [(size_t)NNODE * GG];
__device__ __align__(16) float g_h1 [(size_t)NNODE * GG];
__device__ __align__(16) float g_h2 [(size_t)NNODE * GG];
__device__ __align__(16) float g_tgt[(size_t)TT * BB * (2 * GG)];
__device__ __align__(16) float g_gi [(size_t)TT * BB * (3 * HH)];
__device__ __align__(16) float g_wihT[(size_t)(2 * GG) * (3 * HH)];   // 256 x 384
__device__ __align__(16) float g_whhT[(size_t)HH * (3 * HH)];         // 128 x 384
__device__ __align__(16) float g_gruh[(size_t)BB * HH];
__device__ __align__(16) float g_outs[(size_t)TT * BB * HH];
__device__ __align__(16) float g_val [NNZ];
__device__ __align__(16) float g_dinv[NNODE];
__device__ __align__(16) int   g_col [NNZ];
__device__ __align__(16) int   g_rowptr[NNODE + 1];
__device__ __align__(16) int   g_deg [NNODE];
__device__ __align__(16) int   g_fill[NNODE];
__device__ __align__(16) int   g_src [NE];
__device__ __align__(16) int   g_dst [NE];
__device__ __align__(16) int   g_ti  [BB];
__device__ int g_is64;

// ------------------------- index dtype detection + conversion -------------------------
// If the index buffer is int64 (values < 2^31), every odd 32-bit word is zero.
__global__ void k_detect(const unsigned int* __restrict__ w, int n_elems) {
    __shared__ int bad;
    if (threadIdx.x == 0) bad = 0;
    __syncthreads();
    int limit = n_elems < 4096 ? n_elems : 4096;
    for (int i = threadIdx.x; i < limit; i += blockDim.x)
        if (w[2 * i + 1] != 0u) bad = 1;
    __syncthreads();
    if (threadIdx.x == 0) g_is64 = bad ? 0 : 1;
}

__device__ __forceinline__ int clampN(int v) {
    return v < 0 ? 0 : (v >= NNODE ? NNODE - 1 : v);
}

__global__ void k_cvt_edges(const void* __restrict__ ei) {
    int e = blockIdx.x * blockDim.x + threadIdx.x;
    if (e < NE) {
        int s, d;
        if (g_is64) {
            const long long* p = (const long long*)ei;
            s = (int)p[e]; d = (int)p[NE + e];
        } else {
            const int* p = (const int*)ei;
            s = p[e]; d = p[NE + e];
        }
        g_src[e] = clampN(s);
        g_dst[e] = clampN(d);
    }
}

__global__ void k_cvt_ti(const void* __restrict__ ti) {
    int b = blockIdx.x * blockDim.x + threadIdx.x;
    if (b < BB) {
        int v;
        if (g_is64) v = (int)((const long long*)ti)[b];
        else        v = ((const int*)ti)[b];
        g_ti[b] = clampN(v);
    }
}

// ------------------------- graph preprocessing -------------------------
__global__ void k_init_deg() {
    int i = blockIdx.x * blockDim.x + threadIdx.x;
    if (i < NNODE) { g_deg[i] = 1; g_fill[i] = 0; }   // self loop counts 1
}

__global__ void k_deg_edges() {
    int e = blockIdx.x * blockDim.x + threadIdx.x;
    if (e < NE) atomicAdd(&g_deg[g_dst[e]], 1);
}

__global__ void k_dinv() {
    int i = blockIdx.x * blockDim.x + threadIdx.x;
    if (i < NNODE) g_dinv[i] = rsqrtf((float)g_deg[i]);
}

// one block, 1024 threads, chunked shfl scan (exclusive) of g_deg -> g_rowptr
__global__ void k_scan() {
    const int CH = 40;                       // 1024*40 = 40960 >= NNODE
    int t = threadIdx.x;
    int lane = t & 31, wid = t >> 5;
    int beg = t * CH;
    int sum = 0;
    for (int i = 0; i < CH; i++) {
        int idx = beg + i;
        if (idx < NNODE) sum += g_deg[idx];
    }
    int v = sum;
    for (int o = 1; o < 32; o <<= 1) {
        int u = __shfl_up_sync(0xffffffffu, v, o);
        if (lane >= o) v += u;
    }
    __shared__ int wsum[32];
    if (lane == 31) wsum[wid] = v;
    __syncthreads();
    if (wid == 0) {
        int w = wsum[lane];
        for (int o = 1; o < 32; o <<= 1) {
            int u = __shfl_up_sync(0xffffffffu, w, o);
            if (lane >= o) w += u;
        }
        wsum[lane] = w;
    }
    __syncthreads();
    int run = v - sum + (wid > 0 ? wsum[wid - 1] : 0);   // exclusive prefix for this chunk
    for (int i = 0; i < CH; i++) {
        int idx = beg + i;
        if (idx < NNODE) {
            g_rowptr[idx] = run;
            run += g_deg[idx];
        }
    }
    if (t == 1023) g_rowptr[NNODE] = run;
}

__global__ void k_selfloop() {
    int n = blockIdx.x * blockDim.x + threadIdx.x;
    if (n < NNODE) {
        int pos = g_rowptr[n];
        g_col[pos] = n;
        float d = g_dinv[n];
        g_val[pos] = d * d;
        g_fill[n] = 1;
    }
}

__global__ void k_fill_edges() {
    int e = blockIdx.x * blockDim.x + threadIdx.x;
    if (e < NE) {
        int s = g_src[e];
        int d = g_dst[e];
        int pos = g_rowptr[d] + atomicAdd(&g_fill[d], 1);
        g_col[pos] = s;
        g_val[pos] = g_dinv[s] * g_dinv[d];
    }
}

// ------------------------- SGEMM (128x128x16 tile, 8x8/thread) -------------------------
// Compile-time buffer selection: AS/BS/CS pick __device__ symbols (or external arg when 0).
// C[M,N] = op(A[M,K] @ B[K,N] + bias). N % 128 == 0, K % 16 == 0, M guarded.
template<int AS, int BS, int CS, bool RELU, bool BIAS>
__global__ void sgemm128(const float* __restrict__ Aext,
                         const float* __restrict__ Bext,
                         const float* __restrict__ bias,
                         int M, int N, int K)
{
    const float* A;
    if constexpr (AS == 1)      A = g_h;
    else if constexpr (AS == 2) A = g_h1;
    else if constexpr (AS == 3) A = g_tgt;
    else                        A = Aext;
    const float* B;
    if constexpr (BS == 1)      B = g_wihT;
    else                        B = Bext;
    float* C;
    if constexpr (CS == 1)      C = g_h;
    else if constexpr (CS == 2) C = g_m;
    else                        C = g_gi;

    const int BM = 128, BN = 128, BK = 16, TM = 8, TN = 8;
    __shared__ __align__(16) float As[BK][BM];
    __shared__ __align__(16) float Bs[BK][BN];
    int tid = threadIdx.x;                 // 256 threads
    int tx = tid % 16, ty = tid / 16;
    int rowBase = blockIdx.y * BM;
    int colBase = blockIdx.x * BN;

    float acc[TM][TN];
#pragma unroll
    for (int i = 0; i < TM; i++)
#pragma unroll
        for (int j = 0; j < TN; j++) acc[i][j] = 0.f;

    int aRow = tid >> 2;                   // 0..63
    int aCol = (tid & 3) * 4;              // 0,4,8,12
    int bRow = tid >> 5;                   // 0..7
    int bCol = (tid & 31) * 4;             // 0..124

    for (int k0 = 0; k0 < K; k0 += BK) {
#pragma unroll
        for (int p = 0; p < 2; p++) {
            int r = aRow + p * 64;
            int gr = rowBase + r;
            float4 v = make_float4(0.f, 0.f, 0.f, 0.f);
            if (gr < M) v = *(const float4*)(A + (size_t)gr * K + k0 + aCol);
            As[aCol + 0][r] = v.x; As[aCol + 1][r] = v.y;
            As[aCol + 2][r] = v.z; As[aCol + 3][r] = v.w;
        }
#pragma unroll
        for (int p = 0; p < 2; p++) {
            int r = bRow + p * 8;
            float4 v = *(const float4*)(B + (size_t)(k0 + r) * N + colBase + bCol);
            *(float4*)&Bs[r][bCol] = v;
        }
        __syncthreads();
#pragma unroll
        for (int kk = 0; kk < BK; kk++) {
            float a[TM], b[TN];
#pragma unroll
            for (int i = 0; i < TM; i++) a[i] = As[kk][ty * TM + i];
#pragma unroll
            for (int j = 0; j < TN; j++) b[j] = Bs[kk][tx * TN + j];
#pragma unroll
            for (int i = 0; i < TM; i++)
#pragma unroll
                for (int j = 0; j < TN; j++) acc[i][j] = fmaf(a[i], b[j], acc[i][j]);
        }
        __syncthreads();
    }

#pragma unroll
    for (int i = 0; i < TM; i++) {
        int gr = rowBase + ty * TM + i;
        if (gr >= M) continue;
#pragma unroll
        for (int j = 0; j < TN; j += 4) {
            int gc = colBase + tx * TN + j;
            float4 o;
            o.x = acc[i][j]; o.y = acc[i][j + 1]; o.z = acc[i][j + 2]; o.w = acc[i][j + 3];
            if (BIAS) {
                o.x += bias[gc]; o.y += bias[gc + 1]; o.z += bias[gc + 2]; o.w += bias[gc + 3];
            }
            if (RELU) {
                o.x = fmaxf(o.x, 0.f); o.y = fmaxf(o.y, 0.f);
                o.z = fmaxf(o.z, 0.f); o.w = fmaxf(o.w, 0.f);
            }
            *(float4*)(C + (size_t)gr * N + gc) = o;
        }
    }
}

// ------------------------- GCN aggregation: warp per dst node -------------------------
// reads g_m, writes g_h1 (OUT=1) or g_h2 (OUT=2)
template<int OUT>
__global__ void k_agg(const float* __restrict__ bias)
{
    float* out;
    if constexpr (OUT == 1) out = g_h1;
    else                    out = g_h2;
    int warp = (blockIdx.x * blockDim.x + threadIdx.x) >> 5;
    int lane = threadIdx.x & 31;
    if (warp >= NNODE) return;
    int s0 = g_rowptr[warp], s1 = g_rowptr[warp + 1];
    const float4* m4 = (const float4*)g_m;
    float4 acc = make_float4(0.f, 0.f, 0.f, 0.f);
    for (int e = s0; e < s1; e++) {
        float v = g_val[e];
        float4 t = m4[(size_t)g_col[e] * 32 + lane];
        acc.x = fmaf(v, t.x, acc.x); acc.y = fmaf(v, t.y, acc.y);
        acc.z = fmaf(v, t.z, acc.z); acc.w = fmaf(v, t.w, acc.w);
    }
    int c = lane * 4;
    acc.x = fmaxf(acc.x + bias[c + 0], 0.f);
    acc.y = fmaxf(acc.y + bias[c + 1], 0.f);
    acc.z = fmaxf(acc.z + bias[c + 2], 0.f);
    acc.w = fmaxf(acc.w + bias[c + 3], 0.f);
    ((float4*)out)[(size_t)warp * 32 + lane] = acc;
}

// ------------------------- gather targets -------------------------
__global__ void k_gather(int t) {
    int b = blockIdx.x;
    int f = threadIdx.x;                   // 256
    int node = g_ti[b];
    float v = (f < GG) ? g_h1[(size_t)node * GG + f]
                       : g_h2[(size_t)node * GG + (f - GG)];
    g_tgt[((size_t)t * BB + b) * (2 * GG) + f] = v;
}

// ------------------------- weight transposes / zero -------------------------
__global__ void k_transpose_wih(const float* __restrict__ w) {  // (384,256) -> (256,384)
    int i = blockIdx.x * blockDim.x + threadIdx.x;
    if (i < 384 * 256) {
        int jj = i / 256, k = i % 256;
        g_wihT[(size_t)k * 384 + jj] = w[i];
    }
}
__global__ void k_transpose_whh(const float* __restrict__ w) {  // (384,128) -> (128,384)
    int i = blockIdx.x * blockDim.x + threadIdx.x;
    if (i < 384 * 128) {
        int jj = i / 128, k = i % 128;
        g_whhT[(size_t)k * 384 + jj] = w[i];
    }
}
__global__ void k_zero_h0() {
    int i = blockIdx.x * blockDim.x + threadIdx.x;
    if (i < BB * HH) g_gruh[i] = 0.f;
}

// ------------------------- GRU step -------------------------
__device__ __forceinline__ float sigmoidf_(float x) { return 1.f / (1.f + expf(-x)); }

__global__ void k_gru_step(int t, const float* __restrict__ b_hh) {
    int b = blockIdx.x;            // 1024
    int j = threadIdx.x;           // 128
    __shared__ float sh[HH];
    sh[j] = g_gruh[(size_t)b * HH + j];
    __syncthreads();
    float hr = b_hh[j], hz = b_hh[HH + j], hg = b_hh[2 * HH + j];
#pragma unroll 4
    for (int k = 0; k < HH; k++) {
        float hk = sh[k];
        hr = fmaf(hk, g_whhT[(size_t)k * 384 + j], hr);
        hz = fmaf(hk, g_whhT[(size_t)k * 384 + HH + j], hz);
        hg = fmaf(hk, g_whhT[(size_t)k * 384 + 2 * HH + j], hg);
    }
    size_t gib = ((size_t)t * BB + b) * (3 * HH);
    float r = sigmoidf_(g_gi[gib + j] + hr);
    float z = sigmoidf_(g_gi[gib + HH + j] + hz);
    float g = tanhf(g_gi[gib + 2 * HH + j] + r * hg);
    float hn = (1.f - z) * g + z * sh[j];
    g_gruh[(size_t)b * HH + j] = hn;
    g_outs[((size_t)t * BB + b) * HH + j] = hn;
}

// ------------------------- attention + prediction head -------------------------
__global__ void k_final(const float* __restrict__ attn_w, const float* __restrict__ attn_b,
                        const float* __restrict__ pw1, const float* __restrict__ pb1,
                        const float* __restrict__ pw2, const float* __restrict__ pb2,
                        float* __restrict__ out)
{
    int b = blockIdx.x;            // 1024
    int j = threadIdx.x;           // 128
    __shared__ float so[TT][HH];
    __shared__ float red[HH];
    __shared__ float sc[TT];
    __shared__ float w8[TT];
    __shared__ float hm[16];

#pragma unroll
    for (int t = 0; t < TT; t++) so[t][j] = g_outs[((size_t)t * BB + b) * HH + j];
    float aw = attn_w[j];
    __syncthreads();

    for (int t = 0; t < TT; t++) {
        red[j] = so[t][j] * aw;
        __syncthreads();
        for (int off = 64; off > 0; off >>= 1) {
            if (j < off) red[j] += red[j + off];
            __syncthreads();
        }
        if (j == 0) sc[t] = tanhf(red[0] + attn_b[0]);
        __syncthreads();
    }
    if (j == 0) {
        float mx = sc[0];
        for (int t = 1; t < TT; t++) mx = fmaxf(mx, sc[t]);
        float s = 0.f;
        for (int t = 0; t < TT; t++) { w8[t] = expf(sc[t] - mx); s += w8[t]; }
        float inv = 1.f / s;
        for (int t = 0; t < TT; t++) w8[t] *= inv;
    }
    __syncthreads();
    float rep = 0.f;
#pragma unroll
    for (int t = 0; t < TT; t++) rep = fmaf(w8[t], so[t][j], rep);
    red[j] = rep;
    __syncthreads();
    if (j < 16) {
        float s = pb1[j];
        for (int k = 0; k < HH; k++) s = fmaf(red[k], pw1[k * 16 + j], s);
        hm[j] = fmaxf(s, 0.f);
    }
    __syncthreads();
    if (j == 0) {
        float p = pb2[0];
#pragma unroll
        for (int k = 0; k < 16; k++) p = fmaf(hm[k], pw2[k], p);
        out[b] = p;
    }
    if (j < TT) out[BB + b * TT + j] = w8[j];
}

// ------------------------- launch -------------------------
extern "C" void kernel_launch(void* const* d_in, const int* in_sizes, int n_in,
                              void* d_out, int out_size)
{
    const float* x       = (const float*)d_in[0];
    const void*  ei      = d_in[1];
    const void*  ti      = d_in[2];
    const float* proj_w  = (const float*)d_in[3];
    const float* proj_b  = (const float*)d_in[4];
    const float* gcn_w1  = (const float*)d_in[5];
    const float* gcn_b1  = (const float*)d_in[6];
    const float* gcn_w2  = (const float*)d_in[7];
    const float* gcn_b2  = (const float*)d_in[8];
    const float* gru_w_ih = (const float*)d_in[9];
    const float* gru_w_hh = (const float*)d_in[10];
    const float* gru_b_ih = (const float*)d_in[11];
    const float* gru_b_hh = (const float*)d_in[12];
    const float* attn_w  = (const float*)d_in[13];
    const float* attn_b  = (const float*)d_in[14];
    const float* pred_w1 = (const float*)d_in[15];
    const float* pred_b1 = (const float*)d_in[16];
    const float* pred_w2 = (const float*)d_in[17];
    const float* pred_b2 = (const float*)d_in[18];
    float* out = (float*)d_out;

    // ---- index dtype detection + conversion (int32 vs int64, clamped) ----
    k_detect<<<1, 1024>>>((const unsigned int*)ei, BB);   // probe using smallest plausible span
    k_cvt_edges<<<(NE + 255) / 256, 256>>>(ei);
    k_cvt_ti<<<(BB + 255) / 256, 256>>>(ti);

    // ---- graph preprocessing (CSR with self loops) ----
    k_init_deg<<<(NNODE + 255) / 256, 256>>>();
    k_deg_edges<<<(NE + 255) / 256, 256>>>();
    k_dinv<<<(NNODE + 255) / 256, 256>>>();
    k_scan<<<1, 1024>>>();
    k_selfloop<<<(NNODE + 255) / 256, 256>>>();
    k_fill_edges<<<(NE + 255) / 256, 256>>>();

    // ---- GRU weight prep ----
    k_transpose_wih<<<(384 * 256 + 255) / 256, 256>>>(gru_w_ih);
    k_transpose_whh<<<(384 * 128 + 255) / 256, 256>>>(gru_w_hh);
    k_zero_h0<<<(BB * HH + 255) / 256, 256>>>();

    const int aggBlocks = (NNODE * 32 + 255) / 256;
    dim3 gProj(1, (NNODE + 127) / 128);           // N=128
    dim3 gGcn(1, (NNODE + 127) / 128);            // N=128

    for (int t = 0; t < TT; t++) {
        const float* xt = x + (size_t)t * NNODE * FF;
        // h = relu(x_t @ proj_w + proj_b)            (A ext, C = g_h)
        sgemm128<0, 0, 1, true, true><<<gProj, 256>>>(xt, proj_w, proj_b, NNODE, PP, FF);
        // m = h @ gcn_w1                             (A = g_h, C = g_m)
        sgemm128<1, 0, 2, false, false><<<gGcn, 256>>>(nullptr, gcn_w1, nullptr, NNODE, GG, PP);
        // h1 = relu(agg(m) + b1)
        k_agg<1><<<aggBlocks, 256>>>(gcn_b1);
        // m = h1 @ gcn_w2                            (A = g_h1, C = g_m)
        sgemm128<2, 0, 2, false, false><<<gGcn, 256>>>(nullptr, gcn_w2, nullptr, NNODE, GG, GG);
        // h2 = relu(agg(m) + b2)
        k_agg<2><<<aggBlocks, 256>>>(gcn_b2);
        // gather targets into tgt[t]
        k_gather<<<BB, 256>>>(t);
    }

    // GI = tgt (8192 x 256) @ wihT (256 x 384) + b_ih   (A = g_tgt, B = g_wihT, C = g_gi)
    dim3 gGi(3, (TT * BB + 127) / 128);
    sgemm128<3, 1, 3, false, true><<<gGi, 256>>>(nullptr, nullptr, gru_b_ih, TT * BB, 3 * HH, 2 * GG);

    for (int t = 0; t < TT; t++)
        k_gru_step<<<BB, HH>>>(t, gru_b_hh);

    k_final<<<BB, HH>>>(attn_w, attn_b, pred_w1, pred_b1, pred_w2, pred_b2, out);
}